// round 13
// baseline (speedup 1.0000x reference)
#include <cuda_runtime.h>
#include <cuda_fp16.h>
#include <cstdint>

// Problem dims (fixed)
#define BB 4
#define TT 4096
#define EE 1024
#define HH 64
#define BT (BB * TT)          // 16384 rows
#define SCALE 0.03125f        // E^-0.5

// Scratch (device globals)
__device__ float g_Q[BT * HH];
__device__ float g_M[BB * HH * HH];
__device__ __half g_WT[192 * EE];   // [n][k]; n: q 0-63, k 64-127, v 128-191

// ---------------------------------------------------------------------------
// PTX helpers (baseline PTX, valid under compute_103)
// ---------------------------------------------------------------------------
#define MMA_FP16(c, a, b)                                                     \
    asm volatile(                                                             \
        "mma.sync.aligned.m16n8k16.row.col.f32.f16.f16.f32 "                  \
        "{%0,%1,%2,%3}, {%4,%5,%6,%7}, {%8,%9}, {%0,%1,%2,%3};\n"             \
        : "+f"(c[0]), "+f"(c[1]), "+f"(c[2]), "+f"(c[3])                      \
        : "r"(a[0]), "r"(a[1]), "r"(a[2]), "r"(a[3]), "r"(b[0]), "r"(b[1]))

#define LDSM4(r0, r1, r2, r3, addr)                                           \
    asm volatile("ldmatrix.sync.aligned.m8n8.x4.shared.b16 {%0,%1,%2,%3}, [%4];" \
        : "=r"(r0), "=r"(r1), "=r"(r2), "=r"(r3) : "r"(addr))

#define CP_ASYNC16(dst, src) \
    asm volatile("cp.async.cg.shared.global [%0], [%1], 16;" :: "r"(dst), "l"(src))
#define CP_COMMIT() asm volatile("cp.async.commit_group;")
#define CP_WAIT0()  asm volatile("cp.async.wait_group 0;")

__device__ __forceinline__ uint32_t smem_u32(const void* p) {
    uint32_t a;
    asm("{ .reg .u64 t; cvta.to.shared.u64 t, %1; cvt.u32.u64 %0, t; }" : "=r"(a) : "l"(p));
    return a;
}

// ---------------------------------------------------------------------------
// Prep: many small blocks. Blocks 0..191: 16k x 64n transpose tiles of
// Wq|Wk|Wv -> fp16 g_WT[n][k]. Blocks 192..207: zero g_M via float4.
// ---------------------------------------------------------------------------
__global__ __launch_bounds__(256) void prep_kernel(
    const float* __restrict__ Wq,
    const float* __restrict__ Wk,
    const float* __restrict__ Wv)
{
    const int t = threadIdx.x;
    const int bx = blockIdx.x;
    if (bx >= 192) {
        int i = (bx - 192) * 256 + t;
        ((float4*)g_M)[i] = make_float4(0.f, 0.f, 0.f, 0.f);
        return;
    }
    __shared__ float Ws[16][65];
    const int m  = bx >> 6;              // 0=Wq, 1=Wk, 2=Wv
    const int k0 = (bx & 63) * 16;
    const float* W = (m == 0) ? Wq : (m == 1) ? Wk : Wv;

#pragma unroll
    for (int l = 0; l < 4; l++) {
        int f = t + l * 256;             // 0..1023
        int row = f >> 6;                // k-local 0..15
        int col = f & 63;                // n
        Ws[row][col] = W[(size_t)(k0 + row) * HH + col];
    }
    __syncthreads();
#pragma unroll
    for (int l = 0; l < 4; l++) {
        int f = t + l * 256;
        int n  = f >> 4;                 // 0..63
        int kk = f & 15;
        g_WT[(size_t)(m * 64 + n) * EE + k0 + kk] = __float2half_rn(Ws[kk][n]);
    }
}

// ---------------------------------------------------------------------------
// Fused QKV + K^T V: block = 64 rows x 192 cols, single fp16 pass, BK=64.
// grid = 256, 8 warps (2M x 4N), warp tile 32x48.
// Smem per buffer (36864B): Xh 64x144B @0, Wh 192x144B @9216.
// Two buffers = 73728 B (needs attr). Epilogue reuses pool: Ks/Vs [64][68].
// ---------------------------------------------------------------------------
#define BUFS 36864
#define QKV_SMEM (2 * BUFS)

__global__ __launch_bounds__(256) void qkv_mma_kernel(
    const float* __restrict__ X,
    const float* __restrict__ bq,
    const float* __restrict__ bkk,
    const float* __restrict__ bv)
{
    extern __shared__ __align__(16) char sm[];
    const uint32_t sb = smem_u32(sm);
    const int t    = threadIdx.x;
    const int warp = t >> 5;
    const int lane = t & 31;
    const int g    = lane >> 2;
    const int tig  = lane & 3;
    const int wm   = warp >> 2;      // 0..1 -> m offset 32*wm
    const int wn   = warp & 3;       // 0..3 -> n offset 48*wn
    const int m0   = blockIdx.x * 64;
    const int batch = m0 >> 12;

    const float4* X4 = (const float4*)X;

    float c[2][6][4];
#pragma unroll
    for (int mt = 0; mt < 2; mt++)
#pragma unroll
        for (int nt = 0; nt < 6; nt++)
#pragma unroll
            for (int j = 0; j < 4; j++) c[mt][nt][j] = 0.f;

    float4 xr[4];
    const int xrow = t >> 2;         // 0..63 (one row per thread)
    const int xq   = t & 3;          // 16-fp32 chunk within 64-col tile

    // prefetch X tile (k0, 64 cols) into registers: 4 float4 per thread
    auto ldgX = [&](int k0) {
#pragma unroll
        for (int j = 0; j < 4; j++)
            xr[j] = X4[(size_t)(m0 + xrow) * (EE / 4) + (k0 >> 2) + xq * 4 + j];
    };
    // convert 16 fp32 -> 16 fp16, store as 2 uint4
    auto stX = [&](int buf) {
        char* xh = sm + buf * BUFS;
        uint32_t h[8];
#pragma unroll
        for (int j = 0; j < 4; j++) {
            __half2 p0 = __floats2half2_rn(xr[j].x, xr[j].y);
            __half2 p1 = __floats2half2_rn(xr[j].z, xr[j].w);
            h[2 * j]     = *(uint32_t*)&p0;
            h[2 * j + 1] = *(uint32_t*)&p1;
        }
        int off = xrow * 144 + xq * 32;
        *(uint4*)(xh + off)      = make_uint4(h[0], h[1], h[2], h[3]);
        *(uint4*)(xh + off + 16) = make_uint4(h[4], h[5], h[6], h[7]);
    };
    // W tile: 192 rows x 64 cols fp16 = 1536 x 16B chunks, 6 per thread
    auto cpW = [&](int k0, int buf) {
        uint32_t wbase = sb + buf * BUFS + 9216;
#pragma unroll
        for (int j = 0; j < 6; j++) {
            int cc = t + j * 256;          // 0..1535
            int row = cc >> 3;             // 0..191
            int q = cc & 7;                // 16B chunk within 128B row
            const __half* src = g_WT + (size_t)row * EE + k0 + q * 8;
            uint32_t dst = wbase + row * 144 + q * 16;
            CP_ASYNC16(dst, src);
        }
    };
    // 4 ks-steps of k16: ldmatrix + 48 MMAs
    auto domma = [&](int buf) {
        uint32_t xh = sb + buf * BUFS;
#pragma unroll
        for (int ks = 0; ks < 4; ks++) {
            const int kboff = ks * 32;     // bytes
            uint32_t a[2][4], bh[6][2];
#pragma unroll
            for (int mt = 0; mt < 2; mt++) {
                uint32_t addr = xh + (uint32_t)((wm * 32 + mt * 16 + (lane & 15)) * 144
                                                + kboff + (lane >> 4) * 16);
                LDSM4(a[mt][0], a[mt][1], a[mt][2], a[mt][3], addr);
            }
#pragma unroll
            for (int nb = 0; nb < 3; nb++) {
                uint32_t addr = xh + 9216 + (uint32_t)((wn * 48 + nb * 16 + (lane & 15)) * 144
                                                       + kboff + (lane >> 4) * 16);
                uint32_t r0, r1, r2, r3;
                LDSM4(r0, r1, r2, r3, addr);
                bh[nb * 2][0] = r0; bh[nb * 2][1] = r2;
                bh[nb * 2 + 1][0] = r1; bh[nb * 2 + 1][1] = r3;
            }
#pragma unroll
            for (int mt = 0; mt < 2; mt++)
#pragma unroll
                for (int nt = 0; nt < 6; nt++)
                    MMA_FP16(c[mt][nt], a[mt], bh[nt]);
        }
    };

    // ---- pipelined mainloop: 16 tiles of BK=64 ----
    ldgX(0);
    cpW(0, 0);
    CP_COMMIT();
    stX(0);
    for (int i = 0; i < 16; i++) {
        int buf = i & 1;
        CP_WAIT0();
        __syncthreads();
        if (i < 15) {
            ldgX((i + 1) * 64);
            cpW((i + 1) * 64, buf ^ 1);
            CP_COMMIT();
        }
        domma(buf);
        if (i < 15) stX(buf ^ 1);
    }
    __syncthreads();   // smem reusable for K/V staging

    // ---- epilogue: Q -> g_Q; K,V -> smem; K^T V -> atomicAdd g_M ----
    float* Ks = (float*)sm;               // [64][68]
    float* Vs = (float*)(sm + 17408);     // [64][68]
#pragma unroll
    for (int mt = 0; mt < 2; mt++) {
        int r = wm * 32 + mt * 16 + g;
#pragma unroll
        for (int nt = 0; nt < 6; nt++) {
            int nbase = wn * 48 + nt * 8;
            int which = nbase >> 6;              // 0=Q, 1=K, 2=V
            int nc    = (nbase & 63) + 2 * tig;
            if (which == 0) {
                float b0v = bq[nc];
                float b1v = bq[nc + 1];
                float2 o0 = {c[mt][nt][0] + b0v, c[mt][nt][1] + b1v};
                float2 o1 = {c[mt][nt][2] + b0v, c[mt][nt][3] + b1v};
                *(float2*)&g_Q[(size_t)(m0 + r) * HH + nc] = o0;
                *(float2*)&g_Q[(size_t)(m0 + r + 8) * HH + nc] = o1;
            } else {
                const float* bias = (which == 1) ? bkk : bv;
                float* S = (which == 1) ? Ks : Vs;
                float b0v = bias[nc];
                float b1v = bias[nc + 1];
                S[r * 68 + nc]           = c[mt][nt][0] + b0v;
                S[r * 68 + nc + 1]       = c[mt][nt][1] + b1v;
                S[(r + 8) * 68 + nc]     = c[mt][nt][2] + b0v;
                S[(r + 8) * 68 + nc + 1] = c[mt][nt][3] + b1v;
            }
        }
    }
    __syncthreads();

    {
        const int i0 = (t >> 4) * 4;
        const int j0 = (t & 15) * 4;
        float acc[4][4];
#pragma unroll
        for (int i = 0; i < 4; i++)
#pragma unroll
            for (int j = 0; j < 4; j++) acc[i][j] = 0.f;
#pragma unroll 8
        for (int s = 0; s < 64; s++) {
            float4 kk = *(const float4*)&Ks[s * 68 + i0];
            float4 vv = *(const float4*)&Vs[s * 68 + j0];
            float a[4] = {kk.x, kk.y, kk.z, kk.w};
            float b2[4] = {vv.x, vv.y, vv.z, vv.w};
#pragma unroll
            for (int i = 0; i < 4; i++)
#pragma unroll
                for (int j = 0; j < 4; j++)
                    acc[i][j] += a[i] * b2[j];
        }
        float* Mb = g_M + (size_t)batch * HH * HH;
#pragma unroll
        for (int i = 0; i < 4; i++)
#pragma unroll
            for (int j = 0; j < 4; j++)
                atomicAdd(&Mb[(i0 + i) * HH + j0 + j], acc[i][j]);
    }
}

// ---------------------------------------------------------------------------
// out[b] = SCALE * Q[b] @ M[b].  32 rows per block -> grid BT/32 = 512.
// ---------------------------------------------------------------------------
__global__ __launch_bounds__(256) void out_kernel(float* __restrict__ out)
{
    __shared__ float Ms[64][68];
    __shared__ float Qs[32][68];

    const int t    = threadIdx.x;
    const int tx   = t & 15;
    const int ty   = t >> 4;
    const int row0 = blockIdx.x * 32;
    const int b    = row0 / TT;

    const float4* Q4 = (const float4*)(g_Q + (size_t)row0 * HH);
    const float4* M4 = (const float4*)(g_M + (size_t)b * HH * HH);

    // Q: 32x16 float4 = 512 -> 2/thread; M: 1024 float4 -> 4/thread
#pragma unroll
    for (int l = 0; l < 2; l++) {
        int f   = t + l * 256;
        int row = f >> 4;
        int c4  = f & 15;
        *(float4*)&Qs[row][c4 * 4] = Q4[(size_t)row * 16 + c4];
    }
#pragma unroll
    for (int l = 0; l < 4; l++) {
        int f   = t + l * 256;
        int row = f >> 4;
        int c4  = f & 15;
        *(float4*)&Ms[row][c4 * 4] = M4[(size_t)row * 16 + c4];
    }
    __syncthreads();

    // each thread: 2 rows x 4 cols
    float acc[2][4];
#pragma unroll
    for (int i = 0; i < 2; i++)
#pragma unroll
        for (int j = 0; j < 4; j++) acc[i][j] = 0.f;

#pragma unroll 4
    for (int k0 = 0; k0 < 64; k0 += 4) {
        float4 q4[2];
#pragma unroll
        for (int i = 0; i < 2; i++)
            q4[i] = *(const float4*)&Qs[ty * 2 + i][k0];
#pragma unroll
        for (int kk = 0; kk < 4; kk++) {
            float4 m4 = *(const float4*)&Ms[k0 + kk][tx * 4];
            float m[4] = {m4.x, m4.y, m4.z, m4.w};
#pragma unroll
            for (int i = 0; i < 2; i++) {
                float qv = (kk == 0) ? q4[i].x : (kk == 1) ? q4[i].y
                         : (kk == 2) ? q4[i].z : q4[i].w;
#pragma unroll
                for (int j = 0; j < 4; j++)
                    acc[i][j] += qv * m[j];
            }
        }
    }

#pragma unroll
    for (int i = 0; i < 2; i++) {
        int r = row0 + ty * 2 + i;
        float4 o;
        o.x = acc[i][0] * SCALE;
        o.y = acc[i][1] * SCALE;
        o.z = acc[i][2] * SCALE;
        o.w = acc[i][3] * SCALE;
        *(float4*)&out[(size_t)r * HH + tx * 4] = o;
    }
}

// ---------------------------------------------------------------------------
// Launch
// ---------------------------------------------------------------------------
extern "C" void kernel_launch(void* const* d_in, const int* in_sizes, int n_in,
                              void* d_out, int out_size)
{
    const float* idx = (const float*)d_in[0];
    const float* Wq  = (const float*)d_in[1];
    const float* bq  = (const float*)d_in[2];
    const float* Wk  = (const float*)d_in[3];
    const float* bk  = (const float*)d_in[4];
    const float* Wv  = (const float*)d_in[5];
    const float* bv  = (const float*)d_in[6];
    float* out = (float*)d_out;

    static bool attr_set = false;
    if (!attr_set) {
        cudaFuncSetAttribute(qkv_mma_kernel,
                             cudaFuncAttributeMaxDynamicSharedMemorySize, QKV_SMEM);
        attr_set = true;
    }

    prep_kernel<<<208, 256>>>(Wq, Wk, Wv);

    qkv_mma_kernel<<<BT / 64, 256, QKV_SMEM>>>(idx, bq, bk, bv);

    out_kernel<<<BT / 32, 256>>>(out);
}

// round 14
// speedup vs baseline: 1.4573x; 1.4573x over previous
#include <cuda_runtime.h>
#include <cuda_fp16.h>
#include <cstdint>

// Problem dims (fixed)
#define BB 4
#define TT 4096
#define EE 1024
#define HH 64
#define BT (BB * TT)          // 16384 rows
#define SCALE 0.03125f        // E^-0.5

// Scratch (device globals)
__device__ float g_Q[BT * HH];
__device__ float g_M[BB * HH * HH];
__device__ __half g_WT[192 * EE];   // [n][k]; n: q 0-63, k 64-127, v 128-191

// ---------------------------------------------------------------------------
// PTX helpers (baseline PTX, valid under compute_103)
// ---------------------------------------------------------------------------
#define MMA_FP16(c, a, b)                                                     \
    asm volatile(                                                             \
        "mma.sync.aligned.m16n8k16.row.col.f32.f16.f16.f32 "                  \
        "{%0,%1,%2,%3}, {%4,%5,%6,%7}, {%8,%9}, {%0,%1,%2,%3};\n"             \
        : "+f"(c[0]), "+f"(c[1]), "+f"(c[2]), "+f"(c[3])                      \
        : "r"(a[0]), "r"(a[1]), "r"(a[2]), "r"(a[3]), "r"(b[0]), "r"(b[1]))

#define LDSM4(r0, r1, r2, r3, addr)                                           \
    asm volatile("ldmatrix.sync.aligned.m8n8.x4.shared.b16 {%0,%1,%2,%3}, [%4];" \
        : "=r"(r0), "=r"(r1), "=r"(r2), "=r"(r3) : "r"(addr))

#define CP_ASYNC16(dst, src) \
    asm volatile("cp.async.cg.shared.global [%0], [%1], 16;" :: "r"(dst), "l"(src))
#define CP_COMMIT() asm volatile("cp.async.commit_group;")
#define CP_WAIT0()  asm volatile("cp.async.wait_group 0;")
#define CP_WAIT1()  asm volatile("cp.async.wait_group 1;")

__device__ __forceinline__ uint32_t smem_u32(const void* p) {
    uint32_t a;
    asm("{ .reg .u64 t; cvta.to.shared.u64 t, %1; cvt.u32.u64 %0, t; }" : "=r"(a) : "l"(p));
    return a;
}

// ---------------------------------------------------------------------------
// Prep: many small blocks. Blocks 0..191: 16k x 64n transpose tiles of
// Wq|Wk|Wv -> fp16 g_WT[n][k]. Blocks 192..207: zero g_M via float4.
// ---------------------------------------------------------------------------
__global__ __launch_bounds__(256) void prep_kernel(
    const float* __restrict__ Wq,
    const float* __restrict__ Wk,
    const float* __restrict__ Wv)
{
    const int t = threadIdx.x;
    const int bx = blockIdx.x;
    if (bx >= 192) {
        int i = (bx - 192) * 256 + t;
        ((float4*)g_M)[i] = make_float4(0.f, 0.f, 0.f, 0.f);
        return;
    }
    __shared__ float Ws[16][65];
    const int m  = bx >> 6;              // 0=Wq, 1=Wk, 2=Wv
    const int k0 = (bx & 63) * 16;
    const float* W = (m == 0) ? Wq : (m == 1) ? Wk : Wv;

#pragma unroll
    for (int l = 0; l < 4; l++) {
        int f = t + l * 256;             // 0..1023
        int row = f >> 6;                // k-local 0..15
        int col = f & 63;                // n
        Ws[row][col] = W[(size_t)(k0 + row) * HH + col];
    }
    __syncthreads();
#pragma unroll
    for (int l = 0; l < 4; l++) {
        int f = t + l * 256;
        int n  = f >> 4;                 // 0..63
        int kk = f & 15;
        g_WT[(size_t)(m * 64 + n) * EE + k0 + kk] = __float2half_rn(Ws[kk][n]);
    }
}

// ---------------------------------------------------------------------------
// Fused QKV + K^T V: block = 64 rows x 192 cols, single fp16 pass, BK=32.
// 3-stage cp.async pipeline (wait_group 1): tile i+2's W copies in flight
// while tile i computes. grid = 256, 8 warps (2M x 4N), warp tile 32x48.
// Smem per buffer (20480B): Xh 64x80B @0, Wh 192x80B @5120. 3 bufs = 61440.
// Epilogue reuses pool: Ks[64][68] @0 + Vs[64][68] @17408 = 34816 B.
// ---------------------------------------------------------------------------
#define BUFS 20480
#define QKV_SMEM (3 * BUFS)

__global__ __launch_bounds__(256) void qkv_mma_kernel(
    const float* __restrict__ X,
    const float* __restrict__ bq,
    const float* __restrict__ bkk,
    const float* __restrict__ bv)
{
    extern __shared__ __align__(16) char sm[];
    const uint32_t sb = smem_u32(sm);
    const int t    = threadIdx.x;
    const int warp = t >> 5;
    const int lane = t & 31;
    const int g    = lane >> 2;
    const int tig  = lane & 3;
    const int wm   = warp >> 2;      // 0..1 -> m offset 32*wm
    const int wn   = warp & 3;       // 0..3 -> n offset 48*wn
    const int m0   = blockIdx.x * 64;
    const int batch = m0 >> 12;

    const float4* X4 = (const float4*)X;

    float c[2][6][4];
#pragma unroll
    for (int mt = 0; mt < 2; mt++)
#pragma unroll
        for (int nt = 0; nt < 6; nt++)
#pragma unroll
            for (int j = 0; j < 4; j++) c[mt][nt][j] = 0.f;

    float4 xr[2];
    const int xrow = t >> 2;         // 0..63
    const int xc4  = (t & 3) * 2;    // float4 chunks xc4, xc4+1

    auto ldgX = [&](int k0) {
#pragma unroll
        for (int j = 0; j < 2; j++)
            xr[j] = X4[(size_t)(m0 + xrow) * (EE / 4) + (k0 >> 2) + xc4 + j];
    };
    auto stX = [&](int buf) {
        char* xh = sm + buf * BUFS;
#pragma unroll
        for (int j = 0; j < 2; j++) {
            __half2 p0 = __floats2half2_rn(xr[j].x, xr[j].y);
            __half2 p1 = __floats2half2_rn(xr[j].z, xr[j].w);
            int off = xrow * 80 + (xc4 + j) * 8;
            *(uint2*)(xh + off) = make_uint2(*(uint32_t*)&p0, *(uint32_t*)&p1);
        }
    };
    // W tile: 192 rows x 32 cols fp16 = 768 x 16B, 3/thread
    auto cpW = [&](int k0, int buf) {
        uint32_t wbase = sb + buf * BUFS + 5120;
#pragma unroll
        for (int j = 0; j < 3; j++) {
            int cc = t + j * 256;          // 0..767
            int row = cc >> 2;             // 0..191
            int q = cc & 3;
            const __half* src = g_WT + (size_t)row * EE + k0 + q * 8;
            uint32_t dst = wbase + row * 80 + q * 16;
            CP_ASYNC16(dst, src);
        }
    };
    auto domma = [&](int buf) {
        uint32_t xh = sb + buf * BUFS;
#pragma unroll
        for (int ks = 0; ks < 2; ks++) {
            const int kboff = ks * 32;
            uint32_t a[2][4], bh[6][2];
#pragma unroll
            for (int mt = 0; mt < 2; mt++) {
                uint32_t addr = xh + (uint32_t)((wm * 32 + mt * 16 + (lane & 15)) * 80
                                                + kboff + (lane >> 4) * 16);
                LDSM4(a[mt][0], a[mt][1], a[mt][2], a[mt][3], addr);
            }
#pragma unroll
            for (int nb = 0; nb < 3; nb++) {
                uint32_t addr = xh + 5120 + (uint32_t)((wn * 48 + nb * 16 + (lane & 15)) * 80
                                                       + kboff + (lane >> 4) * 16);
                uint32_t r0, r1, r2, r3;
                LDSM4(r0, r1, r2, r3, addr);
                bh[nb * 2][0] = r0; bh[nb * 2][1] = r2;
                bh[nb * 2 + 1][0] = r1; bh[nb * 2 + 1][1] = r3;
            }
#pragma unroll
            for (int mt = 0; mt < 2; mt++)
#pragma unroll
                for (int nt = 0; nt < 6; nt++)
                    MMA_FP16(c[mt][nt], a[mt], bh[nt]);
        }
    };

    // ---- 3-stage pipelined mainloop: 32 tiles of BK=32 ----
    ldgX(0);
    cpW(0, 0);
    CP_COMMIT();
    stX(0);
    ldgX(32);
    cpW(32, 1);
    CP_COMMIT();
    stX(1);
    for (int i = 0; i < 32; i++) {
        int buf = i % 3;
        if (i >= 31) { CP_WAIT0(); } else { CP_WAIT1(); }
        __syncthreads();
        if (i < 30) {
            int nb = (i + 2) % 3;
            ldgX((i + 2) * 32);
            cpW((i + 2) * 32, nb);
            CP_COMMIT();
            domma(buf);
            stX(nb);
        } else {
            domma(buf);
        }
    }
    __syncthreads();   // smem reusable for K/V staging

    // ---- epilogue: Q -> g_Q; K,V -> smem; K^T V -> atomicAdd g_M ----
    float* Ks = (float*)sm;               // [64][68]
    float* Vs = (float*)(sm + 17408);     // [64][68]
#pragma unroll
    for (int mt = 0; mt < 2; mt++) {
        int r = wm * 32 + mt * 16 + g;
#pragma unroll
        for (int nt = 0; nt < 6; nt++) {
            int nbase = wn * 48 + nt * 8;
            int which = nbase >> 6;              // 0=Q, 1=K, 2=V
            int nc    = (nbase & 63) + 2 * tig;
            if (which == 0) {
                float b0v = bq[nc];
                float b1v = bq[nc + 1];
                float2 o0 = {c[mt][nt][0] + b0v, c[mt][nt][1] + b1v};
                float2 o1 = {c[mt][nt][2] + b0v, c[mt][nt][3] + b1v};
                *(float2*)&g_Q[(size_t)(m0 + r) * HH + nc] = o0;
                *(float2*)&g_Q[(size_t)(m0 + r + 8) * HH + nc] = o1;
            } else {
                const float* bias = (which == 1) ? bkk : bv;
                float* S = (which == 1) ? Ks : Vs;
                float b0v = bias[nc];
                float b1v = bias[nc + 1];
                S[r * 68 + nc]           = c[mt][nt][0] + b0v;
                S[r * 68 + nc + 1]       = c[mt][nt][1] + b1v;
                S[(r + 8) * 68 + nc]     = c[mt][nt][2] + b0v;
                S[(r + 8) * 68 + nc + 1] = c[mt][nt][3] + b1v;
            }
        }
    }
    __syncthreads();

    {
        const int i0 = (t >> 4) * 4;
        const int j0 = (t & 15) * 4;
        float acc[4][4];
#pragma unroll
        for (int i = 0; i < 4; i++)
#pragma unroll
            for (int j = 0; j < 4; j++) acc[i][j] = 0.f;
#pragma unroll 8
        for (int s = 0; s < 64; s++) {
            float4 kk = *(const float4*)&Ks[s * 68 + i0];
            float4 vv = *(const float4*)&Vs[s * 68 + j0];
            float a[4] = {kk.x, kk.y, kk.z, kk.w};
            float b2[4] = {vv.x, vv.y, vv.z, vv.w};
#pragma unroll
            for (int i = 0; i < 4; i++)
#pragma unroll
                for (int j = 0; j < 4; j++)
                    acc[i][j] += a[i] * b2[j];
        }
        float* Mb = g_M + (size_t)batch * HH * HH;
#pragma unroll
        for (int i = 0; i < 4; i++)
#pragma unroll
            for (int j = 0; j < 4; j++)
                atomicAdd(&Mb[(i0 + i) * HH + j0 + j], acc[i][j]);
    }
}

// ---------------------------------------------------------------------------
// out[b] = SCALE * Q[b] @ M[b].  32 rows per block -> grid BT/32 = 512.
// ---------------------------------------------------------------------------
__global__ __launch_bounds__(256) void out_kernel(float* __restrict__ out)
{
    __shared__ float Ms[64][68];
    __shared__ float Qs[32][68];

    const int t    = threadIdx.x;
    const int tx   = t & 15;
    const int ty   = t >> 4;
    const int row0 = blockIdx.x * 32;
    const int b    = row0 / TT;

    const float4* Q4 = (const float4*)(g_Q + (size_t)row0 * HH);
    const float4* M4 = (const float4*)(g_M + (size_t)b * HH * HH);

#pragma unroll
    for (int l = 0; l < 2; l++) {
        int f   = t + l * 256;
        int row = f >> 4;
        int c4  = f & 15;
        *(float4*)&Qs[row][c4 * 4] = Q4[(size_t)row * 16 + c4];
    }
#pragma unroll
    for (int l = 0; l < 4; l++) {
        int f   = t + l * 256;
        int row = f >> 4;
        int c4  = f & 15;
        *(float4*)&Ms[row][c4 * 4] = M4[(size_t)row * 16 + c4];
    }
    __syncthreads();

    float acc[2][4];
#pragma unroll
    for (int i = 0; i < 2; i++)
#pragma unroll
        for (int j = 0; j < 4; j++) acc[i][j] = 0.f;

#pragma unroll 4
    for (int k0 = 0; k0 < 64; k0 += 4) {
        float4 q4[2];
#pragma unroll
        for (int i = 0; i < 2; i++)
            q4[i] = *(const float4*)&Qs[ty * 2 + i][k0];
#pragma unroll
        for (int kk = 0; kk < 4; kk++) {
            float4 m4 = *(const float4*)&Ms[k0 + kk][tx * 4];
            float m[4] = {m4.x, m4.y, m4.z, m4.w};
#pragma unroll
            for (int i = 0; i < 2; i++) {
                float qv = (kk == 0) ? q4[i].x : (kk == 1) ? q4[i].y
                         : (kk == 2) ? q4[i].z : q4[i].w;
#pragma unroll
                for (int j = 0; j < 4; j++)
                    acc[i][j] += qv * m[j];
            }
        }
    }

#pragma unroll
    for (int i = 0; i < 2; i++) {
        int r = row0 + ty * 2 + i;
        float4 o;
        o.x = acc[i][0] * SCALE;
        o.y = acc[i][1] * SCALE;
        o.z = acc[i][2] * SCALE;
        o.w = acc[i][3] * SCALE;
        *(float4*)&out[(size_t)r * HH + tx * 4] = o;
    }
}

// ---------------------------------------------------------------------------
// Launch
// ---------------------------------------------------------------------------
extern "C" void kernel_launch(void* const* d_in, const int* in_sizes, int n_in,
                              void* d_out, int out_size)
{
    const float* idx = (const float*)d_in[0];
    const float* Wq  = (const float*)d_in[1];
    const float* bq  = (const float*)d_in[2];
    const float* Wk  = (const float*)d_in[3];
    const float* bk  = (const float*)d_in[4];
    const float* Wv  = (const float*)d_in[5];
    const float* bv  = (const float*)d_in[6];
    float* out = (float*)d_out;

    static bool attr_set = false;
    if (!attr_set) {
        cudaFuncSetAttribute(qkv_mma_kernel,
                             cudaFuncAttributeMaxDynamicSharedMemorySize, QKV_SMEM);
        attr_set = true;
    }

    prep_kernel<<<208, 256>>>(Wq, Wk, Wv);

    qkv_mma_kernel<<<BT / 64, 256, QKV_SMEM>>>(idx, bq, bk, bv);

    out_kernel<<<BT / 32, 256>>>(out);
}